// round 11
// baseline (speedup 1.0000x reference)
#include <cuda_runtime.h>
#include <cuda_fp16.h>
#include <cstdint>

#define D        64
#define ITERS    4
#define OUTC     ((ITERS + 1) * D)   // 320 output columns
#define N_MAX    50016               // padded
#define E_MAX    800000
#define TPB      256

// -------- scratch (__device__ globals; no allocation allowed) --------
__device__ int    g_deg[N_MAX];          // in-degree
__device__ int    g_rowptr[N_MAX + 1];   // CSR row pointers (by dst)
__device__ int    g_cursor[N_MAX];       // placement cursors
__device__ int    g_src[E_MAX];
__device__ int    g_dst[E_MAX];
__device__ int    g_col[E_MAX];          // CSR columns (src grouped by dst)
__device__ int    g_is64;                // 1 if edge_index is int64
__device__ __half g_xh0[N_MAX * D];      // fp16 shadow (ping)
__device__ __half g_xh1[N_MAX * D];      // fp16 shadow (pong)

// ---------------- kernels ----------------

// Fused: zero g_deg everywhere; block 0 additionally detects index dtype.
__global__ void init_kernel(const int* __restrict__ p32, int n_nodes,
                            int n_check) {
    int i = blockIdx.x * blockDim.x + threadIdx.x;
    if (i < n_nodes) g_deg[i] = 0;
    if (blockIdx.x == 0) {
        __shared__ int zc;
        if (threadIdx.x == 0) zc = 0;
        __syncthreads();
        int cnt = 0;
        for (int j = threadIdx.x; j < n_check; j += blockDim.x)
            if (p32[2 * j + 1] == 0) cnt++;
        atomicAdd(&zc, cnt);
        __syncthreads();
        if (threadIdx.x == 0) g_is64 = (zc > (n_check * 9) / 10) ? 1 : 0;
    }
}

// Fused: normalize indices + degree histogram + copy x into out slab 0
// (fp32) and g_xh0 (fp16).
__global__ void convert_copy_kernel(const int* __restrict__ p32,
                                    const float* __restrict__ x,
                                    float* __restrict__ out,
                                    int n_edges, int n_nodes) {
    int t = blockIdx.x * blockDim.x + threadIdx.x;

    if (t < n_edges) {
        int s, d;
        if (g_is64) {
            s = p32[2 * t];
            d = p32[2 * ((size_t)n_edges + t)];
        } else {
            s = p32[t];
            d = p32[n_edges + t];
        }
        g_src[t] = s;
        g_dst[t] = d;
        atomicAdd(&g_deg[d], 1);
    }

    int i = t >> 4;
    int lane = t & 15;                    // 16 lanes x float4 = 64 floats
    if (i < n_nodes) {
        float4 v = reinterpret_cast<const float4*>(x + (size_t)i * D)[lane];
        reinterpret_cast<float4*>(out + (size_t)i * OUTC)[lane] = v;
        __half2 h0 = __float22half2_rn(make_float2(v.x, v.y));
        __half2 h1 = __float22half2_rn(make_float2(v.z, v.w));
        uint2 hw;
        hw.x = *reinterpret_cast<unsigned*>(&h0);
        hw.y = *reinterpret_cast<unsigned*>(&h1);
        reinterpret_cast<uint2*>(g_xh0 + (size_t)i * D)[lane] = hw;
    }
}

// Single-block two-pass exclusive scan of g_deg -> g_rowptr (+ cursors).
__global__ void scan_kernel(int n_nodes, int n_edges) {
    __shared__ int sm[TPB];
    int chunk = (n_nodes + TPB - 1) / TPB;
    int base = threadIdx.x * chunk;
    int lim = min(base + chunk, n_nodes);

    int sum = 0;
    for (int i = base; i < lim; i++) sum += g_deg[i];
    sm[threadIdx.x] = sum;
    __syncthreads();
    for (int off = 1; off < TPB; off <<= 1) {
        int v = (threadIdx.x >= off) ? sm[threadIdx.x - off] : 0;
        __syncthreads();
        sm[threadIdx.x] += v;
        __syncthreads();
    }
    int run = sm[threadIdx.x] - sum;      // exclusive offset for this chunk
    for (int i = base; i < lim; i++) {
        g_rowptr[i] = run;
        g_cursor[i] = run;
        run += g_deg[i];
    }
    if (threadIdx.x == TPB - 1) g_rowptr[n_nodes] = n_edges;
}

// Place src ids into CSR order (by dst).
__global__ void place_kernel(int n_edges) {
    int e = blockIdx.x * blockDim.x + threadIdx.x;
    if (e >= n_edges) return;
    int d = g_dst[e];
    int pos = atomicAdd(&g_cursor[d], 1);
    g_col[pos] = g_src[e];
}

// Fused pull + combine, fp16 gather. Ping-pong shadow slabs are selected
// INSIDE device code via `parity` (a __device__ symbol's address is only
// valid in device code — passing it from host was the R10 bug).
//   out_k[i] = 0.5 * ( out_{k-1}[i] + (1/max(deg,1)) * sum_j xh[col[j]] )
// 8 threads per node; each lane owns 8 features (16 B fp16 per neighbor).
__global__ void pull_kernel(const float* __restrict__ xin,   // out + (k-1)*D
                            float* __restrict__ xout,        // out + k*D
                            int n_nodes, int parity, int write_half) {
    const __half* __restrict__ xh_in  = parity ? g_xh1 : g_xh0;
    __half*       __restrict__ xh_out = parity ? g_xh0 : g_xh1;

    int t = blockIdx.x * blockDim.x + threadIdx.x;
    int i = t >> 3;
    int lane = t & 7;
    if (i >= n_nodes) return;
    int start = g_rowptr[i];
    int end   = g_rowptr[i + 1];

    float a0 = 0.f, a1 = 0.f, a2 = 0.f, a3 = 0.f;
    float a4 = 0.f, a5 = 0.f, a6 = 0.f, a7 = 0.f;

#pragma unroll 4
    for (int j = start; j < end; j++) {
        int s = __ldg(&g_col[j]);
        uint4 hw = reinterpret_cast<const uint4*>(xh_in + (size_t)s * D)[lane];
        float2 f0 = __half22float2(*reinterpret_cast<__half2*>(&hw.x));
        float2 f1 = __half22float2(*reinterpret_cast<__half2*>(&hw.y));
        float2 f2 = __half22float2(*reinterpret_cast<__half2*>(&hw.z));
        float2 f3 = __half22float2(*reinterpret_cast<__half2*>(&hw.w));
        a0 += f0.x; a1 += f0.y; a2 += f1.x; a3 += f1.y;
        a4 += f2.x; a5 += f2.y; a6 += f3.x; a7 += f3.y;
    }

    int deg = end - start;
    float inv = 1.0f / (float)(deg > 0 ? deg : 1);
    const float4* xp = reinterpret_cast<const float4*>(xin + (size_t)i * OUTC);
    float4 x0 = xp[lane * 2];
    float4 x1 = xp[lane * 2 + 1];
    float4 r0, r1;
    r0.x = 0.5f * fmaf(a0, inv, x0.x);
    r0.y = 0.5f * fmaf(a1, inv, x0.y);
    r0.z = 0.5f * fmaf(a2, inv, x0.z);
    r0.w = 0.5f * fmaf(a3, inv, x0.w);
    r1.x = 0.5f * fmaf(a4, inv, x1.x);
    r1.y = 0.5f * fmaf(a5, inv, x1.y);
    r1.z = 0.5f * fmaf(a6, inv, x1.z);
    r1.w = 0.5f * fmaf(a7, inv, x1.w);
    float4* op = reinterpret_cast<float4*>(xout + (size_t)i * OUTC);
    op[lane * 2]     = r0;
    op[lane * 2 + 1] = r1;

    if (write_half) {
        __half2 h0 = __float22half2_rn(make_float2(r0.x, r0.y));
        __half2 h1 = __float22half2_rn(make_float2(r0.z, r0.w));
        __half2 h2 = __float22half2_rn(make_float2(r1.x, r1.y));
        __half2 h3 = __float22half2_rn(make_float2(r1.z, r1.w));
        uint4 hw;
        hw.x = *reinterpret_cast<unsigned*>(&h0);
        hw.y = *reinterpret_cast<unsigned*>(&h1);
        hw.z = *reinterpret_cast<unsigned*>(&h2);
        hw.w = *reinterpret_cast<unsigned*>(&h3);
        reinterpret_cast<uint4*>(xh_out + (size_t)i * D)[lane] = hw;
    }
}

// ---------------- launch ----------------

extern "C" void kernel_launch(void* const* d_in, const int* in_sizes, int n_in,
                              void* d_out, int out_size) {
    const float* x   = (const float*)d_in[0];
    const int*   p32 = (const int*)d_in[1];
    float*       out = (float*)d_out;

    const int n_nodes = in_sizes[0] / D;      // 50000
    const int n_edges = in_sizes[1] / 2;      // 800000

    const int nb_nodes = (n_nodes + TPB - 1) / TPB;
    const int big      = (n_edges > n_nodes * 16) ? n_edges : n_nodes * 16;
    const int nb_big   = (big + TPB - 1) / TPB;
    const int nb_edges = (n_edges + TPB - 1) / TPB;

    // 1. init (zero deg + dtype detect)
    init_kernel<<<nb_nodes, TPB>>>(p32, n_nodes, 2048);

    // 2. convert indices + degree + slab-0 copies (fp32 + fp16)
    convert_copy_kernel<<<nb_big, TPB>>>(p32, x, out, n_edges, n_nodes);

    // 3. rowptr scan (single block) + placement
    scan_kernel<<<1, TPB>>>(n_nodes, n_edges);
    place_kernel<<<nb_edges, TPB>>>(n_edges);

    // 4. WL iterations: fused pull + combine, fp16 gather, in-kernel ping-pong
    {
        int threads = n_nodes * 8;
        int blocks = (threads + TPB - 1) / TPB;
        for (int k = 1; k <= ITERS; k++) {
            // k=1 reads g_xh0 (parity 0), writes g_xh1; k=2 parity 1; ...
            pull_kernel<<<blocks, TPB>>>(out + (size_t)(k - 1) * D,
                                         out + (size_t)k * D,
                                         n_nodes, (k - 1) & 1,
                                         (k < ITERS) ? 1 : 0);
        }
    }
}

// round 12
// speedup vs baseline: 1.0021x; 1.0021x over previous
#include <cuda_runtime.h>
#include <cuda_fp16.h>
#include <cstdint>

#define D        64
#define ITERS    4
#define OUTC     ((ITERS + 1) * D)   // 320 output columns
#define N_MAX    50016               // padded
#define E_MAX    800000
#define TPB      256

// -------- scratch (__device__ globals; no allocation allowed) --------
__device__ int    g_deg[N_MAX];          // in-degree
__device__ int    g_rowptr[N_MAX + 1];   // CSR row pointers (by dst)
__device__ int    g_cursor[N_MAX];       // placement cursors
__device__ int    g_src[E_MAX];
__device__ int    g_dst[E_MAX];
__device__ int    g_col[E_MAX];          // CSR columns (src grouped by dst)
__device__ int    g_is64;                // 1 if edge_index is int64
__device__ __half g_xh0[N_MAX * D];      // fp16 shadow (ping)
__device__ __half g_xh1[N_MAX * D];      // fp16 shadow (pong)

// ---------------- kernels ----------------

// Fused: zero g_deg everywhere; block 0 additionally detects index dtype.
__global__ void init_kernel(const int* __restrict__ p32, int n_nodes,
                            int n_check) {
    int i = blockIdx.x * blockDim.x + threadIdx.x;
    if (i < n_nodes) g_deg[i] = 0;
    if (blockIdx.x == 0) {
        __shared__ int zc;
        if (threadIdx.x == 0) zc = 0;
        __syncthreads();
        int cnt = 0;
        for (int j = threadIdx.x; j < n_check; j += blockDim.x)
            if (p32[2 * j + 1] == 0) cnt++;
        atomicAdd(&zc, cnt);
        __syncthreads();
        if (threadIdx.x == 0) g_is64 = (zc > (n_check * 9) / 10) ? 1 : 0;
    }
}

// Fused: normalize indices + degree histogram + copy x into out slab 0
// (fp32) and g_xh0 (fp16).
__global__ void convert_copy_kernel(const int* __restrict__ p32,
                                    const float* __restrict__ x,
                                    float* __restrict__ out,
                                    int n_edges, int n_nodes) {
    int t = blockIdx.x * blockDim.x + threadIdx.x;

    if (t < n_edges) {
        int s, d;
        if (g_is64) {
            s = p32[2 * t];
            d = p32[2 * ((size_t)n_edges + t)];
        } else {
            s = p32[t];
            d = p32[n_edges + t];
        }
        g_src[t] = s;
        g_dst[t] = d;
        atomicAdd(&g_deg[d], 1);
    }

    int i = t >> 4;
    int lane = t & 15;                    // 16 lanes x float4 = 64 floats
    if (i < n_nodes) {
        float4 v = reinterpret_cast<const float4*>(x + (size_t)i * D)[lane];
        reinterpret_cast<float4*>(out + (size_t)i * OUTC)[lane] = v;
        __half2 h0 = __float22half2_rn(make_float2(v.x, v.y));
        __half2 h1 = __float22half2_rn(make_float2(v.z, v.w));
        uint2 hw;
        hw.x = *reinterpret_cast<unsigned*>(&h0);
        hw.y = *reinterpret_cast<unsigned*>(&h1);
        reinterpret_cast<uint2*>(g_xh0 + (size_t)i * D)[lane] = hw;
    }
}

// Single-block two-pass exclusive scan of g_deg -> g_rowptr (+ cursors).
__global__ void scan_kernel(int n_nodes, int n_edges) {
    __shared__ int sm[TPB];
    int chunk = (n_nodes + TPB - 1) / TPB;
    int base = threadIdx.x * chunk;
    int lim = min(base + chunk, n_nodes);

    int sum = 0;
    for (int i = base; i < lim; i++) sum += g_deg[i];
    sm[threadIdx.x] = sum;
    __syncthreads();
    for (int off = 1; off < TPB; off <<= 1) {
        int v = (threadIdx.x >= off) ? sm[threadIdx.x - off] : 0;
        __syncthreads();
        sm[threadIdx.x] += v;
        __syncthreads();
    }
    int run = sm[threadIdx.x] - sum;      // exclusive offset for this chunk
    for (int i = base; i < lim; i++) {
        g_rowptr[i] = run;
        g_cursor[i] = run;
        run += g_deg[i];
    }
    if (threadIdx.x == TPB - 1) g_rowptr[n_nodes] = n_edges;
}

// Place src ids into CSR order (by dst).
__global__ void place_kernel(int n_edges) {
    int e = blockIdx.x * blockDim.x + threadIdx.x;
    if (e >= n_edges) return;
    int d = g_dst[e];
    int pos = atomicAdd(&g_cursor[d], 1);
    g_col[pos] = g_src[e];
}

// Fused pull + combine, fp16 gather, 16 threads/node (restores the 800k-thread
// parallelism that R11 lost — the gather loop is L2-latency-exposed below
// ~25k warps). Each lane owns 4 features: one uint2 (4 halves) per neighbor.
//   out_k[i] = 0.5 * ( out_{k-1}[i] + (1/max(deg,1)) * sum_j xh[col[j]] )
__global__ void pull_kernel(const float* __restrict__ xin,   // out + (k-1)*D
                            float* __restrict__ xout,        // out + k*D
                            int n_nodes, int parity, int write_half) {
    const __half* __restrict__ xh_in  = parity ? g_xh1 : g_xh0;
    __half*       __restrict__ xh_out = parity ? g_xh0 : g_xh1;

    int t = blockIdx.x * blockDim.x + threadIdx.x;
    int i = t >> 4;
    int lane = t & 15;
    if (i >= n_nodes) return;
    int start = g_rowptr[i];
    int end   = g_rowptr[i + 1];

    float a0 = 0.f, a1 = 0.f, a2 = 0.f, a3 = 0.f;

#pragma unroll 8
    for (int j = start; j < end; j++) {
        int s = __ldg(&g_col[j]);
        uint2 hw = reinterpret_cast<const uint2*>(xh_in + (size_t)s * D)[lane];
        float2 f0 = __half22float2(*reinterpret_cast<__half2*>(&hw.x));
        float2 f1 = __half22float2(*reinterpret_cast<__half2*>(&hw.y));
        a0 += f0.x; a1 += f0.y; a2 += f1.x; a3 += f1.y;
    }

    int deg = end - start;
    float inv = 1.0f / (float)(deg > 0 ? deg : 1);
    float4 xv = reinterpret_cast<const float4*>(xin + (size_t)i * OUTC)[lane];
    float4 r;
    r.x = 0.5f * fmaf(a0, inv, xv.x);
    r.y = 0.5f * fmaf(a1, inv, xv.y);
    r.z = 0.5f * fmaf(a2, inv, xv.z);
    r.w = 0.5f * fmaf(a3, inv, xv.w);
    reinterpret_cast<float4*>(xout + (size_t)i * OUTC)[lane] = r;

    if (write_half) {
        __half2 h0 = __float22half2_rn(make_float2(r.x, r.y));
        __half2 h1 = __float22half2_rn(make_float2(r.z, r.w));
        uint2 hw;
        hw.x = *reinterpret_cast<unsigned*>(&h0);
        hw.y = *reinterpret_cast<unsigned*>(&h1);
        reinterpret_cast<uint2*>(xh_out + (size_t)i * D)[lane] = hw;
    }
}

// ---------------- launch ----------------

extern "C" void kernel_launch(void* const* d_in, const int* in_sizes, int n_in,
                              void* d_out, int out_size) {
    const float* x   = (const float*)d_in[0];
    const int*   p32 = (const int*)d_in[1];
    float*       out = (float*)d_out;

    const int n_nodes = in_sizes[0] / D;      // 50000
    const int n_edges = in_sizes[1] / 2;      // 800000

    const int nb_nodes = (n_nodes + TPB - 1) / TPB;
    const int big      = (n_edges > n_nodes * 16) ? n_edges : n_nodes * 16;
    const int nb_big   = (big + TPB - 1) / TPB;
    const int nb_edges = (n_edges + TPB - 1) / TPB;

    // 1. init (zero deg + dtype detect)
    init_kernel<<<nb_nodes, TPB>>>(p32, n_nodes, 2048);

    // 2. convert indices + degree + slab-0 copies (fp32 + fp16)
    convert_copy_kernel<<<nb_big, TPB>>>(p32, x, out, n_edges, n_nodes);

    // 3. rowptr scan (single block) + placement
    scan_kernel<<<1, TPB>>>(n_nodes, n_edges);
    place_kernel<<<nb_edges, TPB>>>(n_edges);

    // 4. WL iterations: fused pull + combine, fp16 gather, in-kernel ping-pong
    {
        int threads = n_nodes * 16;
        int blocks = (threads + TPB - 1) / TPB;
        for (int k = 1; k <= ITERS; k++) {
            pull_kernel<<<blocks, TPB>>>(out + (size_t)(k - 1) * D,
                                         out + (size_t)k * D,
                                         n_nodes, (k - 1) & 1,
                                         (k < ITERS) ? 1 : 0);
        }
    }
}